// round 9
// baseline (speedup 1.0000x reference)
#include <cuda_runtime.h>
#include <math.h>
#include <stdint.h>

#define F 32
#define H 7
#define C 224
#define NRBF 50
#define CUTOFF 5.0f
#define EPSV 1e-8f
#define NMAX 10000
#define EMAX 200000
#define SHS 228   // stage stride (k_mix output)
#define WS  232   // W smem stride (mod 32 == 8 -> conflict-free B frags)
#define HES 40    // he smem stride (mod 32 == 8 -> conflict-free A frags)
#define A2S 124   // edge_in stride (k_edge)

// ---- scratch (device globals: no allocation allowed) ----
__device__ float g_he[EMAX * F];        // per-edge h_ij_edge
__device__ float g_dir[EMAX * 3];       // per-edge direction
__device__ float g_logit[EMAX * H];     // att_w * cut
__device__ float g_tanh[EMAX * C];      // per-edge tanh(hsem @ W)
__device__ float g_m[NMAX * H];         // segment max
__device__ float g_s[NMAX * H];         // segment softmax denom
__device__ int   g_icnt[NMAX];          // edges per node
__device__ int   g_off[NMAX];           // CSR offsets
__device__ int   g_fill[NMAX];          // scatter cursor
__device__ int   g_elist[EMAX];         // edge ids grouped by node
__device__ float g_wt[C * C];           // w_xmix pre-rounded to tf32

__device__ __forceinline__ float siluf(float x) { return x / (1.f + __expf(-x)); }

__device__ __forceinline__ void atomicMaxF(float* addr, float val) {
    int old = __float_as_int(*addr);
    while (__int_as_float(old) < val) {
        int assumed = old;
        old = atomicCAS((int*)addr, assumed, __float_as_int(val));
        if (old == assumed) break;
    }
}

__device__ __forceinline__ uint32_t f2tf(float f) {
    uint32_t o;
    asm("cvt.rna.tf32.f32 %0, %1;" : "=r"(o) : "f"(f));
    return o;
}

#define MMA_TF32(acc, a0, a1, a2, a3, b0, b1)                                  \
    asm volatile(                                                              \
        "mma.sync.aligned.m16n8k8.row.col.f32.tf32.tf32.f32 "                  \
        "{%0,%1,%2,%3}, {%4,%5,%6,%7}, {%8,%9}, {%0,%1,%2,%3};"                \
        : "+f"(acc[0]), "+f"(acc[1]), "+f"(acc[2]), "+f"(acc[3])               \
        : "r"(a0), "r"(a1), "r"(a2), "r"(a3), "r"(b0), "r"(b1))

// ---- K0: init ----
__global__ void k_init(int nN) {
    int stride = gridDim.x * blockDim.x;
    int t0 = blockIdx.x * blockDim.x + threadIdx.x;
    for (int t = t0; t < nN * H; t += stride) { g_m[t] = -1e30f; g_s[t] = 0.f; }
    for (int t = t0; t < nN; t += stride) { g_icnt[t] = 0; g_fill[t] = 0; }
}

// ---- K0b: pre-round w_xmix to tf32 ----
__global__ void k_cvtw(const float* __restrict__ w) {
    int t = blockIdx.x * blockDim.x + threadIdx.x;
    if (t < C * C) g_wt[t] = __uint_as_float(f2tf(w[t]));
}

// ---- K1: edge MLP, block = 32 edges, tensor-core GEMMs ----
__global__ void __launch_bounds__(256) k_edge(
    const float* __restrict__ h, const float* __restrict__ x,
    const int* __restrict__ idx_i, const int* __restrict__ idx_j,
    const float* __restrict__ w_in, const float* __restrict__ b_in,
    const float* __restrict__ w_e1, const float* __restrict__ b_e1,
    const float* __restrict__ w_e2, const float* __restrict__ b_e2,
    const float* __restrict__ w_att, const float* __restrict__ b_att,
    int nE, int nN)
{
    __shared__ float s_wbuf[4352];        // w_in[64x68] -> w_e1[120x36] -> w_e2[32x36]
    __shared__ float s_a2[32 * A2S];      // edge_in [32 x 120] (stride 124)
    __shared__ float s_a3[32 * 36];       // silu(l1)
    __shared__ float s_a4[32 * 36];       // h_edge
    __shared__ float s_watt[32 * 8];
    __shared__ float s_be1[32], s_be2[32], s_batt[8];
    __shared__ float s_d[32];
    __shared__ int   s_i[32], s_j[32];

    int tid = threadIdx.x;
    int warp = tid >> 5, lane = tid & 31;
    int e0 = blockIdx.x * 32;

    if (tid < 32) {
        int e = e0 + tid;
        int ii = -1, jj = -1; float d = 0.f;
        if (e < nE) {
            ii = idx_i[e]; jj = idx_j[e];
            if (ii < 0 || ii >= nN || jj < 0 || jj >= nN) ii = -1;
        }
        if (ii >= 0) {
            float rx = x[jj * 3 + 0] - x[ii * 3 + 0];
            float ry = x[jj * 3 + 1] - x[ii * 3 + 1];
            float rz = x[jj * 3 + 2] - x[ii * 3 + 2];
            d = sqrtf(rx * rx + ry * ry + rz * rz);
            float inv = 1.f / (d + EPSV);
            g_dir[e * 3 + 0] = rx * inv;
            g_dir[e * 3 + 1] = ry * inv;
            g_dir[e * 3 + 2] = rz * inv;
        }
        s_i[tid] = ii; s_j[tid] = (ii >= 0) ? jj : -1; s_d[tid] = d;
    }
    for (int t = tid; t < 64 * 64; t += 256) {
        int k = t >> 6, n = t & 63;
        s_wbuf[k * 68 + n] = (n < NRBF) ? w_in[k * NRBF + n] : 0.f;
    }
    if (tid < 32) { s_be1[tid] = b_e1[tid]; s_be2[tid] = b_e2[tid]; }
    if (tid >= 32 && tid < 40) s_batt[tid - 32] = b_att[tid - 32];
    __syncthreads();

    for (int t = tid; t < 32 * 64; t += 256) {
        int row = t >> 6, col = t & 63;
        int node = (col < 32) ? s_i[row] : s_j[row];
        s_a2[row * A2S + col] = (node >= 0) ? h[node * F + (col & 31)] : 0.f;
    }
    for (int t = tid; t < 32 * 6; t += 256) {
        int row = t / 6, cc = 114 + (t % 6);
        s_a2[row * A2S + cc] = 0.f;
    }
    __syncthreads();

    int wm = warp & 1, wn = warp >> 1;
    int m0 = wm * 16;
    int gid = lane >> 2, tig = lane & 3;

    // GEMM1: h_cat[32x64] @ w_in
    {
        float facc[2][4] = {{0.f,0.f,0.f,0.f},{0.f,0.f,0.f,0.f}};
        for (int k0 = 0; k0 < 64; k0 += 8) {
            const float* ar0 = &s_a2[(m0 + gid) * A2S + k0 + tig];
            const float* ar1 = ar0 + 8 * A2S;
            uint32_t a0 = f2tf(ar0[0]), a1 = f2tf(ar1[0]);
            uint32_t a2 = f2tf(ar0[4]), a3 = f2tf(ar1[4]);
            #pragma unroll
            for (int nt = 0; nt < 2; nt++) {
                int bc = wn * 16 + nt * 8 + gid;
                uint32_t b0 = __float_as_uint(s_wbuf[(k0 + tig) * 68 + bc]);
                uint32_t b1 = __float_as_uint(s_wbuf[(k0 + tig + 4) * 68 + bc]);
                MMA_TF32(facc[nt], a0, a1, a2, a3, b0, b1);
            }
        }
        const float IW = (float)(NRBF - 1) / CUTOFF;
        int r0 = m0 + gid, r1 = r0 + 8;
        float zr0 = s_d[r0] * IW, zr1 = s_d[r1] * IW;
        #pragma unroll
        for (int nt = 0; nt < 2; nt++) {
            int c = wn * 16 + nt * 8 + 2 * tig;
            #pragma unroll
            for (int q = 0; q < 2; q++) {
                int cc = c + q;
                if (cc < NRBF) {
                    float bi = b_in[cc];
                    float z0 = zr0 - (float)cc;
                    float z1 = zr1 - (float)cc;
                    s_a2[r0 * A2S + 64 + cc] = __expf(-0.5f * z0 * z0) * (facc[nt][q] + bi);
                    s_a2[r1 * A2S + 64 + cc] = __expf(-0.5f * z1 * z1) * (facc[nt][2 + q] + bi);
                }
            }
        }
    }
    if (tid < 32) s_a2[tid * A2S + 114] = s_d[tid];
    __syncthreads();

    for (int t = tid; t < 120 * 32; t += 256) {
        int k = t >> 5, n = t & 31;
        s_wbuf[k * 36 + n] = (k < 115) ? w_e1[k * 32 + n] : 0.f;
    }
    __syncthreads();

    // GEMM2
    {
        float acc2[4] = {0.f,0.f,0.f,0.f};
        for (int k0 = 0; k0 < 120; k0 += 8) {
            const float* ar0 = &s_a2[(m0 + gid) * A2S + k0 + tig];
            const float* ar1 = ar0 + 8 * A2S;
            uint32_t a0 = f2tf(ar0[0]), a1 = f2tf(ar1[0]);
            uint32_t a2 = f2tf(ar0[4]), a3 = f2tf(ar1[4]);
            int bc = wn * 8 + gid;
            uint32_t b0 = __float_as_uint(s_wbuf[(k0 + tig) * 36 + bc]);
            uint32_t b1 = __float_as_uint(s_wbuf[(k0 + tig + 4) * 36 + bc]);
            MMA_TF32(acc2, a0, a1, a2, a3, b0, b1);
        }
        int c = wn * 8 + 2 * tig;
        int r0 = m0 + gid, r1 = r0 + 8;
        s_a3[r0 * 36 + c]     = siluf(acc2[0] + s_be1[c]);
        s_a3[r0 * 36 + c + 1] = siluf(acc2[1] + s_be1[c + 1]);
        s_a3[r1 * 36 + c]     = siluf(acc2[2] + s_be1[c]);
        s_a3[r1 * 36 + c + 1] = siluf(acc2[3] + s_be1[c + 1]);
    }
    __syncthreads();

    for (int t = tid; t < 32 * 32; t += 256) {
        int k = t >> 5, n = t & 31;
        s_wbuf[k * 36 + n] = w_e2[k * 32 + n];
    }
    for (int t = tid; t < 32 * 8; t += 256) {
        int q = t >> 3, hh = t & 7;
        s_watt[q * 8 + hh] = (hh < H) ? w_att[q * H + hh] : 0.f;
    }
    __syncthreads();

    // GEMM3
    {
        float acc3[4] = {0.f,0.f,0.f,0.f};
        for (int k0 = 0; k0 < 32; k0 += 8) {
            const float* ar0 = &s_a3[(m0 + gid) * 36 + k0 + tig];
            const float* ar1 = ar0 + 8 * 36;
            uint32_t a0 = f2tf(ar0[0]), a1 = f2tf(ar1[0]);
            uint32_t a2 = f2tf(ar0[4]), a3 = f2tf(ar1[4]);
            int bc = wn * 8 + gid;
            uint32_t b0 = __float_as_uint(s_wbuf[(k0 + tig) * 36 + bc]);
            uint32_t b1 = __float_as_uint(s_wbuf[(k0 + tig + 4) * 36 + bc]);
            MMA_TF32(acc3, a0, a1, a2, a3, b0, b1);
        }
        int c = wn * 8 + 2 * tig;
        int r0 = m0 + gid, r1 = r0 + 8;
        s_a4[r0 * 36 + c]     = acc3[0] + s_be2[c];
        s_a4[r0 * 36 + c + 1] = acc3[1] + s_be2[c + 1];
        s_a4[r1 * 36 + c]     = acc3[2] + s_be2[c];
        s_a4[r1 * 36 + c + 1] = acc3[3] + s_be2[c + 1];
    }
    __syncthreads();

    for (int t = tid; t < 32 * 32; t += 256) {
        int row = t >> 5, col = t & 31;
        int e = e0 + row;
        if (e < nE && s_i[row] >= 0)
            g_he[e * F + col] = s_a4[row * 36 + col];
    }
    if (tid < 32) {
        int e = e0 + tid;
        int i = s_i[tid];
        if (i >= 0) {
            float d = s_d[tid];
            float cut = (d < CUTOFF) ? 0.5f * (__cosf(3.14159265358979f * d / CUTOFF) + 1.f) : 0.f;
            float aw[H];
            #pragma unroll
            for (int hh = 0; hh < H; hh++) aw[hh] = s_batt[hh];
            for (int q = 0; q < F; q++) {
                float v4 = s_a4[tid * 36 + q];
                #pragma unroll
                for (int hh = 0; hh < H; hh++) aw[hh] += v4 * s_watt[q * 8 + hh];
            }
            #pragma unroll
            for (int hh = 0; hh < H; hh++) {
                float a = aw[hh];
                a = a > 0.f ? a : 2.f * (__expf(0.5f * a) - 1.f);
                float wv = a * cut;
                g_logit[e * H + hh] = wv;
                atomicMaxF(&g_m[i * H + hh], wv);
            }
            atomicAdd(&g_icnt[i], 1);
        }
    }
}

// ---- K1b: CSR prefix scan (single block) ----
__global__ void __launch_bounds__(1024) k_scan(int nN) {
    __shared__ int sm[1024];
    int t = threadIdx.x;
    int ch = (nN + 1023) / 1024;
    int base = t * ch;
    int lsum = 0;
    for (int k = 0; k < ch; k++)
        if (base + k < nN) lsum += g_icnt[base + k];
    sm[t] = lsum;
    __syncthreads();
    for (int off = 1; off < 1024; off <<= 1) {
        int v = (t >= off) ? sm[t - off] : 0;
        __syncthreads();
        sm[t] += v;
        __syncthreads();
    }
    int run = (t == 0) ? 0 : sm[t - 1];
    for (int k = 0; k < ch; k++)
        if (base + k < nN) { g_off[base + k] = run; run += g_icnt[base + k]; }
}

// ---- K1c: scatter edge ids into CSR list ----
__global__ void k_scatter(const int* __restrict__ idx_i, int nE, int nN) {
    int e = blockIdx.x * blockDim.x + threadIdx.x;
    if (e >= nE) return;
    int i = idx_i[e];
    if (i < 0 || i >= nN) return;
    int pos = atomicAdd(&g_fill[i], 1);
    g_elist[g_off[i] + pos] = e;
}

// ---- K2: softmax denominators ----
__global__ void k_ssum(const int* __restrict__ idx_i, int nE, int nN) {
    int t = blockIdx.x * blockDim.x + threadIdx.x;
    if (t >= nE * H) return;
    int e = t / H, hh = t - e * H;
    int i = idx_i[e];
    if (i < 0 || i >= nN) return;
    atomicAdd(&g_s[i * H + hh], __expf(g_logit[t] - g_m[i * H + hh]));
}

// ---- K3: xmix GEMM, 64 edges/block, A built on-the-fly from he*att ----
// 8 warps = 4(M16) x 2(N112)
__global__ void __launch_bounds__(256) k_mix(
    const int* __restrict__ idx_i, int nE, int nN)
{
    __shared__ float s_he[64 * HES];     // he tile (stride 40)
    __shared__ float s_att[64 * 8];      // att tile
    __shared__ float wsm[16 * WS];       // W k-slice (stride 232)
    __shared__ float stg[16 * SHS];      // output staging (16 rows)
    int tid = threadIdx.x;
    int e0 = blockIdx.x * 64;

    // load he tile
    for (int t = tid; t < 64 * 32; t += 256) {
        int row = t >> 5, col = t & 31;
        int e = e0 + row;
        s_he[row * HES + col] = (e < nE) ? g_he[e * F + col] : 0.f;
    }
    // load att tile
    for (int t = tid; t < 64 * H; t += 256) {
        int r = t / H, hh = t - r * H;
        int e = e0 + r;
        float a = 0.f;
        if (e < nE) {
            int i = idx_i[e];
            if (i >= 0 && i < nN)
                a = __expf(g_logit[e * H + hh] - g_m[i * H + hh]) / g_s[i * H + hh];
        }
        s_att[r * 8 + hh] = a;
    }

    int warp = tid >> 5, lane = tid & 31;
    int wm = warp >> 1, wn = warp & 1;
    int m0 = wm * 16, n0 = wn * 112;
    int gid = lane >> 2, tig = lane & 3;
    int r0 = m0 + gid, r1 = r0 + 8;

    float acc[14][4];
    #pragma unroll
    for (int nt = 0; nt < 14; nt++)
        #pragma unroll
        for (int q = 0; q < 4; q++) acc[nt][q] = 0.f;

    for (int k0 = 0; k0 < C; k0 += 16) {
        __syncthreads();
        for (int t = tid; t < 16 * 56; t += 256) {
            int r = t / 56, cq = t - r * 56;
            *(float4*)&wsm[r * WS + cq * 4] = *(const float4*)&g_wt[(k0 + r) * C + cq * 4];
        }
        __syncthreads();
        #pragma unroll
        for (int ks = 0; ks < 2; ks++) {
            int kk = ks * 8;
            int kA = k0 + kk + tig;
            int kB = kA + 4;
            int f1 = kA / 7, h1 = kA - f1 * 7;
            int f2 = kB / 7, h2 = kB - f2 * 7;
            uint32_t a0 = f2tf(s_he[r0 * HES + f1] * s_att[r0 * 8 + h1]);
            uint32_t a1 = f2tf(s_he[r1 * HES + f1] * s_att[r1 * 8 + h1]);
            uint32_t a2 = f2tf(s_he[r0 * HES + f2] * s_att[r0 * 8 + h2]);
            uint32_t a3 = f2tf(s_he[r1 * HES + f2] * s_att[r1 * 8 + h2]);
            #pragma unroll
            for (int nt = 0; nt < 14; nt++) {
                int bc = n0 + nt * 8 + gid;
                uint32_t b0 = __float_as_uint(wsm[(kk + tig) * WS + bc]);
                uint32_t b1 = __float_as_uint(wsm[(kk + tig + 4) * WS + bc]);
                MMA_TF32(acc[nt], a0, a1, a2, a3, b0, b1);
            }
        }
    }

    // tanh + store via 16-row staging chunks
    #pragma unroll 1
    for (int ci = 0; ci < 4; ci++) {
        __syncthreads();
        if (wm == ci) {
            #pragma unroll
            for (int nt = 0; nt < 14; nt++) {
                int nb = n0 + nt * 8 + 2 * tig;
                stg[gid * SHS + nb]           = tanhf(acc[nt][0]);
                stg[gid * SHS + nb + 1]       = tanhf(acc[nt][1]);
                stg[(gid + 8) * SHS + nb]     = tanhf(acc[nt][2]);
                stg[(gid + 8) * SHS + nb + 1] = tanhf(acc[nt][3]);
            }
        }
        __syncthreads();
        for (int t = tid; t < 16 * 56; t += 256) {
            int row = t / 56, q = t - row * 56;
            int e = e0 + ci * 16 + row;
            if (e < nE)
                *(float4*)&g_tanh[e * C + q * 4] = *(const float4*)&stg[row * SHS + q * 4];
        }
    }
}

// ---- K4: per-node gather + epilogue (warp per node, no atomics) ----
__global__ void __launch_bounds__(256) k_node(
    const float* __restrict__ h, const float* __restrict__ x, const float* __restrict__ v,
    const float* __restrict__ w_pn1, const float* __restrict__ b_pn1,
    const float* __restrict__ w_pn2, const float* __restrict__ b_pn2,
    const float* __restrict__ w_n1, const float* __restrict__ b_n1,
    const float* __restrict__ w_n2, const float* __restrict__ b_n2,
    const float* __restrict__ w_v1, const float* __restrict__ b_v1,
    const float* __restrict__ w_v2, const float* __restrict__ w_vmix,
    float* __restrict__ out, int nN, int write_xv)
{
    __shared__ float s_cn[8][224];
    __shared__ float s_hs[8][224];
    __shared__ float s_t[8][32];
    __shared__ float s_hh[8][32];
    int warp = threadIdx.x >> 5, lane = threadIdx.x & 31;
    int i = blockIdx.x * 8 + warp;
    if (i >= nN) return;
    int beg = g_off[i], cnt = g_icnt[i];
    float m_l = (lane < H) ? g_m[i * H + lane] : 0.f;
    float sden = (lane < H) ? g_s[i * H + lane] : 1.f;
    int fI[7], hI[7];
    float wv[7];
    #pragma unroll
    for (int k = 0; k < 7; k++) {
        int c = k * 32 + lane;
        fI[k] = c / 7; hI[k] = c - fI[k] * 7;
        wv[k] = w_vmix[c];
    }
    float hisem[7] = {0.f,0.f,0.f,0.f,0.f,0.f,0.f};
    float comb[7][3];
    #pragma unroll
    for (int k = 0; k < 7; k++) { comb[k][0] = 0.f; comb[k][1] = 0.f; comb[k][2] = 0.f; }
    float dvl0 = 0.f, dvl1 = 0.f, dvl2 = 0.f;
    for (int ei = 0; ei < cnt; ei++) {
        int e = g_elist[beg + ei];
        float att_l = 0.f;
        if (lane < H) att_l = __expf(g_logit[e * H + lane] - m_l) / sden;
        float he_l = g_he[e * F + lane];
        float d_l = (lane < 3) ? g_dir[e * 3 + lane] : 0.f;
        float d0 = __shfl_sync(0xffffffffu, d_l, 0);
        float d1 = __shfl_sync(0xffffffffu, d_l, 1);
        float d2 = __shfl_sync(0xffffffffu, d_l, 2);
        float vpl = 0.f;
        #pragma unroll
        for (int k = 0; k < 7; k++) {
            float tv = g_tanh[e * C + k * 32 + lane];
            float hef = __shfl_sync(0xffffffffu, he_l, fI[k]);
            float atth = __shfl_sync(0xffffffffu, att_l, hI[k]);
            hisem[k] += hef * atth;
            comb[k][0] += tv * d0;
            comb[k][1] += tv * d1;
            comb[k][2] += tv * d2;
            vpl += tv * wv[k];
        }
        dvl0 += vpl * d0; dvl1 += vpl * d1; dvl2 += vpl * d2;
    }
    float invc = 1.f / fmaxf((float)cnt, 1.f);
    #pragma unroll
    for (int k = 0; k < 7; k++) {
        int c = k * 32 + lane;
        float c0 = comb[k][0] * invc;
        float c1 = comb[k][1] * invc;
        float c2 = comb[k][2] * invc;
        s_cn[warp][c] = c0 * c0 + c1 * c1 + c2 * c2;
        s_hs[warp][c] = hisem[k];
    }
    #pragma unroll
    for (int off = 16; off > 0; off >>= 1) {
        dvl0 += __shfl_down_sync(0xffffffffu, dvl0, off);
        dvl1 += __shfl_down_sync(0xffffffffu, dvl1, off);
        dvl2 += __shfl_down_sync(0xffffffffu, dvl2, off);
    }
    float dv0 = __shfl_sync(0xffffffffu, dvl0, 0) * invc;
    float dv1 = __shfl_sync(0xffffffffu, dvl1, 0) * invc;
    float dv2 = __shfl_sync(0xffffffffu, dvl2, 0) * invc;
    s_hh[warp][lane] = h[i * F + lane];
    __syncwarp();
    float p1 = b_pn1[lane];
    for (int q = 0; q < C; q++) p1 += s_cn[warp][q] * w_pn1[q * F + lane];
    s_t[warp][lane] = siluf(p1);
    __syncwarp();
    float hsp = b_pn2[lane];
    #pragma unroll
    for (int q = 0; q < F; q++) hsp += s_t[warp][q] * w_pn2[q * F + lane];
    hsp = siluf(hsp);
    __syncwarp();
    s_t[warp][lane] = hsp;
    __syncwarp();
    float n1 = b_n1[lane];
    #pragma unroll
    for (int q = 0; q < F; q++) n1 += s_hh[warp][q] * w_n1[q * F + lane];
    for (int q = 0; q < C; q++) n1 += s_hs[warp][q] * w_n1[(F + q) * F + lane];
    #pragma unroll
    for (int q = 0; q < F; q++) n1 += s_t[warp][q] * w_n1[(F + C + q) * F + lane];
    n1 = siluf(n1);
    __syncwarp();
    s_t[warp][lane] = n1;
    __syncwarp();
    float n2 = b_n2[lane];
    #pragma unroll
    for (int q = 0; q < F; q++) n2 += s_t[warp][q] * w_n2[q * F + lane];
    out[i * F + lane] = s_hh[warp][lane] + siluf(n2);
    float g1 = b_v1[lane];
    #pragma unroll
    for (int q = 0; q < F; q++) g1 += s_hh[warp][q] * w_v1[q * F + lane];
    g1 = siluf(g1);
    float gp = g1 * w_v2[lane];
    #pragma unroll
    for (int off = 16; off > 0; off >>= 1)
        gp += __shfl_xor_sync(0xffffffffu, gp, off);
    float gate = 2.f / (1.f + __expf(-gp));
    if (write_xv && lane < 3) {
        float dv = (lane == 0) ? dv0 : ((lane == 1) ? dv1 : dv2);
        float vu = gate * v[i * 3 + lane] + dv;
        out[nN * F + i * 3 + lane] = x[i * 3 + lane] + vu;
        out[nN * F + nN * 3 + i * 3 + lane] = vu;
    }
}

extern "C" void kernel_launch(void* const* d_in, const int* in_sizes, int n_in,
                              void* d_out, int out_size) {
    const float* h     = (const float*)d_in[0];
    const float* x     = (const float*)d_in[1];
    const float* v     = (const float*)d_in[2];
    const int*   pair  = (const int*)d_in[3];
    const float* w_in  = (const float*)d_in[4];
    const float* b_in  = (const float*)d_in[5];
    const float* w_e1  = (const float*)d_in[6];
    const float* b_e1  = (const float*)d_in[7];
    const float* w_e2  = (const float*)d_in[8];
    const float* b_e2  = (const float*)d_in[9];
    const float* w_att = (const float*)d_in[10];
    const float* b_att = (const float*)d_in[11];
    const float* w_n1  = (const float*)d_in[12];
    const float* b_n1  = (const float*)d_in[13];
    const float* w_n2  = (const float*)d_in[14];
    const float* b_n2  = (const float*)d_in[15];
    const float* w_pn1 = (const float*)d_in[16];
    const float* b_pn1 = (const float*)d_in[17];
    const float* w_pn2 = (const float*)d_in[18];
    const float* b_pn2 = (const float*)d_in[19];
    const float* w_v1  = (const float*)d_in[20];
    const float* b_v1  = (const float*)d_in[21];
    const float* w_v2  = (const float*)d_in[22];
    const float* w_xmix = (const float*)d_in[23];
    const float* w_vmix = (const float*)d_in[24];
    float* out = (float*)d_out;

    int nN = in_sizes[0] / F;
    int nE = in_sizes[3] / 2;
    if (nN > NMAX) nN = NMAX;
    if (nE > EMAX) nE = EMAX;
    const int* idx_i = pair;
    const int* idx_j = pair + nE;
    int write_xv = (out_size >= nN * (F + 6)) ? 1 : 0;

    k_init<<<128, 256>>>(nN);
    k_cvtw<<<(C * C + 255) / 256, 256>>>(w_xmix);
    k_edge<<<(nE + 31) / 32, 256>>>(h, x, idx_i, idx_j, w_in, b_in, w_e1, b_e1,
                                    w_e2, b_e2, w_att, b_att, nE, nN);
    k_scan<<<1, 1024>>>(nN);
    k_scatter<<<(nE + 255) / 256, 256>>>(idx_i, nE, nN);
    k_ssum<<<(nE * H + 255) / 256, 256>>>(idx_i, nE, nN);
    k_mix<<<(nE + 63) / 64, 256>>>(idx_i, nE, nN);
    k_node<<<(nN + 7) / 8, 256>>>(h, x, v, w_pn1, b_pn1, w_pn2, b_pn2,
                                  w_n1, b_n1, w_n2, b_n2, w_v1, b_v1, w_v2,
                                  w_vmix, out, nN, write_xv);
}

// round 10
// speedup vs baseline: 1.1170x; 1.1170x over previous
#include <cuda_runtime.h>
#include <math.h>
#include <stdint.h>

#define F 32
#define H 7
#define C 224
#define NRBF 50
#define CUTOFF 5.0f
#define EPSV 1e-8f
#define NMAX 10000
#define EMAX 200000
#define SHS 228   // A-tile / staging stride (mod 32 == 4: A frags conflict-free)
#define WS  232   // W smem stride (mod 32 == 8: B frags conflict-free)
#define A2S 124   // edge_in stride (k_edge)

// ---- scratch (device globals: no allocation allowed) ----
__device__ float g_he[EMAX * F];        // per-edge h_ij_edge
__device__ float g_dir[EMAX * 3];       // per-edge direction
__device__ float g_logit[EMAX * H];     // att_w * cut
__device__ float g_tanh[EMAX * C];      // per-edge tanh(hsem @ W)
__device__ float g_m[NMAX * H];         // segment max
__device__ float g_s[NMAX * H];         // segment softmax denom
__device__ int   g_icnt[NMAX];          // edges per node
__device__ int   g_off[NMAX];           // CSR offsets
__device__ int   g_fill[NMAX];          // scatter cursor
__device__ int   g_elist[EMAX];         // edge ids grouped by node
__device__ float g_wt[C * C];           // w_xmix pre-rounded to tf32

__device__ __forceinline__ float siluf(float x) { return x / (1.f + __expf(-x)); }

__device__ __forceinline__ void atomicMaxF(float* addr, float val) {
    int old = __float_as_int(*addr);
    while (__int_as_float(old) < val) {
        int assumed = old;
        old = atomicCAS((int*)addr, assumed, __float_as_int(val));
        if (old == assumed) break;
    }
}

__device__ __forceinline__ uint32_t f2tf(float f) {
    uint32_t o;
    asm("cvt.rna.tf32.f32 %0, %1;" : "=r"(o) : "f"(f));
    return o;
}

#define MMA_TF32(acc, a0, a1, a2, a3, b0, b1)                                  \
    asm volatile(                                                              \
        "mma.sync.aligned.m16n8k8.row.col.f32.tf32.tf32.f32 "                  \
        "{%0,%1,%2,%3}, {%4,%5,%6,%7}, {%8,%9}, {%0,%1,%2,%3};"                \
        : "+f"(acc[0]), "+f"(acc[1]), "+f"(acc[2]), "+f"(acc[3])               \
        : "r"(a0), "r"(a1), "r"(a2), "r"(a3), "r"(b0), "r"(b1))

// ---- K0: init ----
__global__ void k_init(int nN) {
    int stride = gridDim.x * blockDim.x;
    int t0 = blockIdx.x * blockDim.x + threadIdx.x;
    for (int t = t0; t < nN * H; t += stride) { g_m[t] = -1e30f; g_s[t] = 0.f; }
    for (int t = t0; t < nN; t += stride) { g_icnt[t] = 0; g_fill[t] = 0; }
}

// ---- K0b: pre-round w_xmix to tf32 ----
__global__ void k_cvtw(const float* __restrict__ w) {
    int t = blockIdx.x * blockDim.x + threadIdx.x;
    if (t < C * C) g_wt[t] = __uint_as_float(f2tf(w[t]));
}

// ---- K1: edge MLP, block = 32 edges, tensor-core GEMMs ----
__global__ void __launch_bounds__(256) k_edge(
    const float* __restrict__ h, const float* __restrict__ x,
    const int* __restrict__ idx_i, const int* __restrict__ idx_j,
    const float* __restrict__ w_in, const float* __restrict__ b_in,
    const float* __restrict__ w_e1, const float* __restrict__ b_e1,
    const float* __restrict__ w_e2, const float* __restrict__ b_e2,
    const float* __restrict__ w_att, const float* __restrict__ b_att,
    int nE, int nN)
{
    __shared__ float s_wbuf[4352];        // w_in[64x68] -> w_e1[120x36] -> w_e2[32x36]
    __shared__ float s_a2[32 * A2S];      // edge_in [32 x 120] (stride 124)
    __shared__ float s_a3[32 * 36];       // silu(l1)
    __shared__ float s_a4[32 * 36];       // h_edge
    __shared__ float s_watt[32 * 8];
    __shared__ float s_be1[32], s_be2[32], s_batt[8];
    __shared__ float s_d[32];
    __shared__ int   s_i[32], s_j[32];

    int tid = threadIdx.x;
    int warp = tid >> 5, lane = tid & 31;
    int e0 = blockIdx.x * 32;

    if (tid < 32) {
        int e = e0 + tid;
        int ii = -1, jj = -1; float d = 0.f;
        if (e < nE) {
            ii = idx_i[e]; jj = idx_j[e];
            if (ii < 0 || ii >= nN || jj < 0 || jj >= nN) ii = -1;
        }
        if (ii >= 0) {
            float rx = x[jj * 3 + 0] - x[ii * 3 + 0];
            float ry = x[jj * 3 + 1] - x[ii * 3 + 1];
            float rz = x[jj * 3 + 2] - x[ii * 3 + 2];
            d = sqrtf(rx * rx + ry * ry + rz * rz);
            float inv = 1.f / (d + EPSV);
            g_dir[e * 3 + 0] = rx * inv;
            g_dir[e * 3 + 1] = ry * inv;
            g_dir[e * 3 + 2] = rz * inv;
        }
        s_i[tid] = ii; s_j[tid] = (ii >= 0) ? jj : -1; s_d[tid] = d;
    }
    for (int t = tid; t < 64 * 64; t += 256) {
        int k = t >> 6, n = t & 63;
        s_wbuf[k * 68 + n] = (n < NRBF) ? w_in[k * NRBF + n] : 0.f;
    }
    if (tid < 32) { s_be1[tid] = b_e1[tid]; s_be2[tid] = b_e2[tid]; }
    if (tid >= 32 && tid < 40) s_batt[tid - 32] = b_att[tid - 32];
    __syncthreads();

    for (int t = tid; t < 32 * 64; t += 256) {
        int row = t >> 6, col = t & 63;
        int node = (col < 32) ? s_i[row] : s_j[row];
        s_a2[row * A2S + col] = (node >= 0) ? h[node * F + (col & 31)] : 0.f;
    }
    for (int t = tid; t < 32 * 6; t += 256) {
        int row = t / 6, cc = 114 + (t % 6);
        s_a2[row * A2S + cc] = 0.f;
    }
    __syncthreads();

    int wm = warp & 1, wn = warp >> 1;
    int m0 = wm * 16;
    int gid = lane >> 2, tig = lane & 3;

    // GEMM1: h_cat[32x64] @ w_in
    {
        float facc[2][4] = {{0.f,0.f,0.f,0.f},{0.f,0.f,0.f,0.f}};
        for (int k0 = 0; k0 < 64; k0 += 8) {
            const float* ar0 = &s_a2[(m0 + gid) * A2S + k0 + tig];
            const float* ar1 = ar0 + 8 * A2S;
            uint32_t a0 = f2tf(ar0[0]), a1 = f2tf(ar1[0]);
            uint32_t a2 = f2tf(ar0[4]), a3 = f2tf(ar1[4]);
            #pragma unroll
            for (int nt = 0; nt < 2; nt++) {
                int bc = wn * 16 + nt * 8 + gid;
                uint32_t b0 = __float_as_uint(s_wbuf[(k0 + tig) * 68 + bc]);
                uint32_t b1 = __float_as_uint(s_wbuf[(k0 + tig + 4) * 68 + bc]);
                MMA_TF32(facc[nt], a0, a1, a2, a3, b0, b1);
            }
        }
        const float IW = (float)(NRBF - 1) / CUTOFF;
        int r0 = m0 + gid, r1 = r0 + 8;
        float zr0 = s_d[r0] * IW, zr1 = s_d[r1] * IW;
        #pragma unroll
        for (int nt = 0; nt < 2; nt++) {
            int c = wn * 16 + nt * 8 + 2 * tig;
            #pragma unroll
            for (int q = 0; q < 2; q++) {
                int cc = c + q;
                if (cc < NRBF) {
                    float bi = b_in[cc];
                    float z0 = zr0 - (float)cc;
                    float z1 = zr1 - (float)cc;
                    s_a2[r0 * A2S + 64 + cc] = __expf(-0.5f * z0 * z0) * (facc[nt][q] + bi);
                    s_a2[r1 * A2S + 64 + cc] = __expf(-0.5f * z1 * z1) * (facc[nt][2 + q] + bi);
                }
            }
        }
    }
    if (tid < 32) s_a2[tid * A2S + 114] = s_d[tid];
    __syncthreads();

    for (int t = tid; t < 120 * 32; t += 256) {
        int k = t >> 5, n = t & 31;
        s_wbuf[k * 36 + n] = (k < 115) ? w_e1[k * 32 + n] : 0.f;
    }
    __syncthreads();

    // GEMM2
    {
        float acc2[4] = {0.f,0.f,0.f,0.f};
        for (int k0 = 0; k0 < 120; k0 += 8) {
            const float* ar0 = &s_a2[(m0 + gid) * A2S + k0 + tig];
            const float* ar1 = ar0 + 8 * A2S;
            uint32_t a0 = f2tf(ar0[0]), a1 = f2tf(ar1[0]);
            uint32_t a2 = f2tf(ar0[4]), a3 = f2tf(ar1[4]);
            int bc = wn * 8 + gid;
            uint32_t b0 = __float_as_uint(s_wbuf[(k0 + tig) * 36 + bc]);
            uint32_t b1 = __float_as_uint(s_wbuf[(k0 + tig + 4) * 36 + bc]);
            MMA_TF32(acc2, a0, a1, a2, a3, b0, b1);
        }
        int c = wn * 8 + 2 * tig;
        int r0 = m0 + gid, r1 = r0 + 8;
        s_a3[r0 * 36 + c]     = siluf(acc2[0] + s_be1[c]);
        s_a3[r0 * 36 + c + 1] = siluf(acc2[1] + s_be1[c + 1]);
        s_a3[r1 * 36 + c]     = siluf(acc2[2] + s_be1[c]);
        s_a3[r1 * 36 + c + 1] = siluf(acc2[3] + s_be1[c + 1]);
    }
    __syncthreads();

    for (int t = tid; t < 32 * 32; t += 256) {
        int k = t >> 5, n = t & 31;
        s_wbuf[k * 36 + n] = w_e2[k * 32 + n];
    }
    for (int t = tid; t < 32 * 8; t += 256) {
        int q = t >> 3, hh = t & 7;
        s_watt[q * 8 + hh] = (hh < H) ? w_att[q * H + hh] : 0.f;
    }
    __syncthreads();

    // GEMM3
    {
        float acc3[4] = {0.f,0.f,0.f,0.f};
        for (int k0 = 0; k0 < 32; k0 += 8) {
            const float* ar0 = &s_a3[(m0 + gid) * 36 + k0 + tig];
            const float* ar1 = ar0 + 8 * 36;
            uint32_t a0 = f2tf(ar0[0]), a1 = f2tf(ar1[0]);
            uint32_t a2 = f2tf(ar0[4]), a3 = f2tf(ar1[4]);
            int bc = wn * 8 + gid;
            uint32_t b0 = __float_as_uint(s_wbuf[(k0 + tig) * 36 + bc]);
            uint32_t b1 = __float_as_uint(s_wbuf[(k0 + tig + 4) * 36 + bc]);
            MMA_TF32(acc3, a0, a1, a2, a3, b0, b1);
        }
        int c = wn * 8 + 2 * tig;
        int r0 = m0 + gid, r1 = r0 + 8;
        s_a4[r0 * 36 + c]     = acc3[0] + s_be2[c];
        s_a4[r0 * 36 + c + 1] = acc3[1] + s_be2[c + 1];
        s_a4[r1 * 36 + c]     = acc3[2] + s_be2[c];
        s_a4[r1 * 36 + c + 1] = acc3[3] + s_be2[c + 1];
    }
    __syncthreads();

    for (int t = tid; t < 32 * 32; t += 256) {
        int row = t >> 5, col = t & 31;
        int e = e0 + row;
        if (e < nE && s_i[row] >= 0)
            g_he[e * F + col] = s_a4[row * 36 + col];
    }
    if (tid < 32) {
        int e = e0 + tid;
        int i = s_i[tid];
        if (i >= 0) {
            float d = s_d[tid];
            float cut = (d < CUTOFF) ? 0.5f * (__cosf(3.14159265358979f * d / CUTOFF) + 1.f) : 0.f;
            float aw[H];
            #pragma unroll
            for (int hh = 0; hh < H; hh++) aw[hh] = s_batt[hh];
            for (int q = 0; q < F; q++) {
                float v4 = s_a4[tid * 36 + q];
                #pragma unroll
                for (int hh = 0; hh < H; hh++) aw[hh] += v4 * s_watt[q * 8 + hh];
            }
            #pragma unroll
            for (int hh = 0; hh < H; hh++) {
                float a = aw[hh];
                a = a > 0.f ? a : 2.f * (__expf(0.5f * a) - 1.f);
                float wv = a * cut;
                g_logit[e * H + hh] = wv;
                atomicMaxF(&g_m[i * H + hh], wv);
            }
            atomicAdd(&g_icnt[i], 1);
        }
    }
}

// ---- K1b: CSR prefix scan (single block) ----
__global__ void __launch_bounds__(1024) k_scan(int nN) {
    __shared__ int sm[1024];
    int t = threadIdx.x;
    int ch = (nN + 1023) / 1024;
    int base = t * ch;
    int lsum = 0;
    for (int k = 0; k < ch; k++)
        if (base + k < nN) lsum += g_icnt[base + k];
    sm[t] = lsum;
    __syncthreads();
    for (int off = 1; off < 1024; off <<= 1) {
        int v = (t >= off) ? sm[t - off] : 0;
        __syncthreads();
        sm[t] += v;
        __syncthreads();
    }
    int run = (t == 0) ? 0 : sm[t - 1];
    for (int k = 0; k < ch; k++)
        if (base + k < nN) { g_off[base + k] = run; run += g_icnt[base + k]; }
}

// ---- K1c: scatter edge ids into CSR list ----
__global__ void k_scatter(const int* __restrict__ idx_i, int nE, int nN) {
    int e = blockIdx.x * blockDim.x + threadIdx.x;
    if (e >= nE) return;
    int i = idx_i[e];
    if (i < 0 || i >= nN) return;
    int pos = atomicAdd(&g_fill[i], 1);
    g_elist[g_off[i] + pos] = e;
}

// ---- K2: softmax denominators ----
__global__ void k_ssum(const int* __restrict__ idx_i, int nE, int nN) {
    int t = blockIdx.x * blockDim.x + threadIdx.x;
    if (t >= nE * H) return;
    int e = t / H, hh = t - e * H;
    int i = idx_i[e];
    if (i < 0 || i >= nN) return;
    atomicAdd(&g_s[i * H + hh], __expf(g_logit[t] - g_m[i * H + hh]));
}

// ---- K3: h_ij_sem, xmix GEMM (tf32 tensor cores), tanh -> g_tanh ----
// block = 32 edges; 8 warps arranged 2(M16) x 4(N56)
__global__ void __launch_bounds__(256) k_mix(
    const int* __restrict__ idx_i, int nE, int nN)
{
    __shared__ float sh[32 * SHS];
    __shared__ float wsm[16 * WS];
    __shared__ float s_att[32][8];
    int tid = threadIdx.x;
    int e0 = blockIdx.x * 32;
    if (tid < 32 * H) {
        int r = tid / H, hh = tid - r * H;
        int e = e0 + r;
        float a = 0.f;
        if (e < nE) {
            int i = idx_i[e];
            if (i >= 0 && i < nN)
                a = __expf(g_logit[e * H + hh] - g_m[i * H + hh]) / g_s[i * H + hh];
        }
        s_att[r][hh] = a;
    }
    __syncthreads();
    {
        int row = tid >> 3, sub = tid & 7;
        int e = e0 + row;
        float* dst = &sh[row * SHS];
        #pragma unroll
        for (int q = 0; q < 4; q++) {
            int f = sub * 4 + q;
            float hv = (e < nE) ? g_he[e * F + f] : 0.f;
            #pragma unroll
            for (int hh = 0; hh < H; hh++)
                dst[f * H + hh] = hv * s_att[row][hh];
        }
    }
    int warp = tid >> 5, lane = tid & 31;
    int wm = warp & 1, wn = warp >> 1;
    int m0 = wm * 16, n0 = wn * 56;
    int gid = lane >> 2, tig = lane & 3;
    float acc[7][4];
    #pragma unroll
    for (int nt = 0; nt < 7; nt++)
        #pragma unroll
        for (int q = 0; q < 4; q++) acc[nt][q] = 0.f;

    for (int k0 = 0; k0 < C; k0 += 16) {
        __syncthreads();
        for (int t = tid; t < 16 * 56; t += 256) {
            int r = t / 56, cq = t - r * 56;
            *(float4*)&wsm[r * WS + cq * 4] = *(const float4*)&g_wt[(k0 + r) * C + cq * 4];
        }
        __syncthreads();
        #pragma unroll
        for (int ks = 0; ks < 2; ks++) {
            int kk = ks * 8;
            const float* arow0 = &sh[(m0 + gid) * SHS + k0 + kk + tig];
            const float* arow1 = arow0 + 8 * SHS;
            uint32_t a0 = f2tf(arow0[0]);
            uint32_t a1 = f2tf(arow1[0]);
            uint32_t a2 = f2tf(arow0[4]);
            uint32_t a3 = f2tf(arow1[4]);
            #pragma unroll
            for (int nt = 0; nt < 7; nt++) {
                int bc = n0 + nt * 8 + gid;
                uint32_t b0 = __float_as_uint(wsm[(kk + tig) * WS + bc]);
                uint32_t b1 = __float_as_uint(wsm[(kk + tig + 4) * WS + bc]);
                MMA_TF32(acc[nt], a0, a1, a2, a3, b0, b1);
            }
        }
    }
    __syncthreads();
    #pragma unroll
    for (int nt = 0; nt < 7; nt++) {
        int nb = n0 + nt * 8 + 2 * tig;
        sh[(m0 + gid) * SHS + nb]         = tanhf(acc[nt][0]);
        sh[(m0 + gid) * SHS + nb + 1]     = tanhf(acc[nt][1]);
        sh[(m0 + gid + 8) * SHS + nb]     = tanhf(acc[nt][2]);
        sh[(m0 + gid + 8) * SHS + nb + 1] = tanhf(acc[nt][3]);
    }
    __syncthreads();
    for (int t = tid; t < 32 * 56; t += 256) {
        int row = t / 56, q = t - row * 56;
        int e = e0 + row;
        if (e < nE)
            *(float4*)&g_tanh[e * C + q * 4] = *(const float4*)&sh[row * SHS + q * 4];
    }
}

// ---- K4: per-node gather + epilogue (warp per node, no atomics) ----
__global__ void __launch_bounds__(256) k_node(
    const float* __restrict__ h, const float* __restrict__ x, const float* __restrict__ v,
    const float* __restrict__ w_pn1, const float* __restrict__ b_pn1,
    const float* __restrict__ w_pn2, const float* __restrict__ b_pn2,
    const float* __restrict__ w_n1, const float* __restrict__ b_n1,
    const float* __restrict__ w_n2, const float* __restrict__ b_n2,
    const float* __restrict__ w_v1, const float* __restrict__ b_v1,
    const float* __restrict__ w_v2, const float* __restrict__ w_vmix,
    float* __restrict__ out, int nN, int write_xv)
{
    __shared__ float s_cn[8][224];
    __shared__ float s_hs[8][224];
    __shared__ float s_t[8][32];
    __shared__ float s_hh[8][32];
    int warp = threadIdx.x >> 5, lane = threadIdx.x & 31;
    int i = blockIdx.x * 8 + warp;
    if (i >= nN) return;
    int beg = g_off[i], cnt = g_icnt[i];
    float m_l = (lane < H) ? g_m[i * H + lane] : 0.f;
    float sden = (lane < H) ? g_s[i * H + lane] : 1.f;
    int fI[7], hI[7];
    float wv[7];
    #pragma unroll
    for (int k = 0; k < 7; k++) {
        int c = k * 32 + lane;
        fI[k] = c / 7; hI[k] = c - fI[k] * 7;
        wv[k] = w_vmix[c];
    }
    float hisem[7] = {0.f,0.f,0.f,0.f,0.f,0.f,0.f};
    float comb[7][3];
    #pragma unroll
    for (int k = 0; k < 7; k++) { comb[k][0] = 0.f; comb[k][1] = 0.f; comb[k][2] = 0.f; }
    float dvl0 = 0.f, dvl1 = 0.f, dvl2 = 0.f;
    for (int ei = 0; ei < cnt; ei++) {
        int e = g_elist[beg + ei];
        float att_l = 0.f;
        if (lane < H) att_l = __expf(g_logit[e * H + lane] - m_l) / sden;
        float he_l = g_he[e * F + lane];
        float d_l = (lane < 3) ? g_dir[e * 3 + lane] : 0.f;
        float d0 = __shfl_sync(0xffffffffu, d_l, 0);
        float d1 = __shfl_sync(0xffffffffu, d_l, 1);
        float d2 = __shfl_sync(0xffffffffu, d_l, 2);
        float vpl = 0.f;
        #pragma unroll
        for (int k = 0; k < 7; k++) {
            float tv = g_tanh[e * C + k * 32 + lane];
            float hef = __shfl_sync(0xffffffffu, he_l, fI[k]);
            float atth = __shfl_sync(0xffffffffu, att_l, hI[k]);
            hisem[k] += hef * atth;
            comb[k][0] += tv * d0;
            comb[k][1] += tv * d1;
            comb[k][2] += tv * d2;
            vpl += tv * wv[k];
        }
        dvl0 += vpl * d0; dvl1 += vpl * d1; dvl2 += vpl * d2;
    }
    float invc = 1.f / fmaxf((float)cnt, 1.f);
    #pragma unroll
    for (int k = 0; k < 7; k++) {
        int c = k * 32 + lane;
        float c0 = comb[k][0] * invc;
        float c1 = comb[k][1] * invc;
        float c2 = comb[k][2] * invc;
        s_cn[warp][c] = c0 * c0 + c1 * c1 + c2 * c2;
        s_hs[warp][c] = hisem[k];
    }
    #pragma unroll
    for (int off = 16; off > 0; off >>= 1) {
        dvl0 += __shfl_down_sync(0xffffffffu, dvl0, off);
        dvl1 += __shfl_down_sync(0xffffffffu, dvl1, off);
        dvl2 += __shfl_down_sync(0xffffffffu, dvl2, off);
    }
    float dv0 = __shfl_sync(0xffffffffu, dvl0, 0) * invc;
    float dv1 = __shfl_sync(0xffffffffu, dvl1, 0) * invc;
    float dv2 = __shfl_sync(0xffffffffu, dvl2, 0) * invc;
    s_hh[warp][lane] = h[i * F + lane];
    __syncwarp();
    float p1 = b_pn1[lane];
    for (int q = 0; q < C; q++) p1 += s_cn[warp][q] * w_pn1[q * F + lane];
    s_t[warp][lane] = siluf(p1);
    __syncwarp();
    float hsp = b_pn2[lane];
    #pragma unroll
    for (int q = 0; q < F; q++) hsp += s_t[warp][q] * w_pn2[q * F + lane];
    hsp = siluf(hsp);
    __syncwarp();
    s_t[warp][lane] = hsp;
    __syncwarp();
    float n1 = b_n1[lane];
    #pragma unroll
    for (int q = 0; q < F; q++) n1 += s_hh[warp][q] * w_n1[q * F + lane];
    for (int q = 0; q < C; q++) n1 += s_hs[warp][q] * w_n1[(F + q) * F + lane];
    #pragma unroll
    for (int q = 0; q < F; q++) n1 += s_t[warp][q] * w_n1[(F + C + q) * F + lane];
    n1 = siluf(n1);
    __syncwarp();
    s_t[warp][lane] = n1;
    __syncwarp();
    float n2 = b_n2[lane];
    #pragma unroll
    for (int q = 0; q < F; q++) n2 += s_t[warp][q] * w_n2[q * F + lane];
    out[i * F + lane] = s_hh[warp][lane] + siluf(n2);
    float g1 = b_v1[lane];
    #pragma unroll
    for (int q = 0; q < F; q++) g1 += s_hh[warp][q] * w_v1[q * F + lane];
    g1 = siluf(g1);
    float gp = g1 * w_v2[lane];
    #pragma unroll
    for (int off = 16; off > 0; off >>= 1)
        gp += __shfl_xor_sync(0xffffffffu, gp, off);
    float gate = 2.f / (1.f + __expf(-gp));
    if (write_xv && lane < 3) {
        float dv = (lane == 0) ? dv0 : ((lane == 1) ? dv1 : dv2);
        float vu = gate * v[i * 3 + lane] + dv;
        out[nN * F + i * 3 + lane] = x[i * 3 + lane] + vu;
        out[nN * F + nN * 3 + i * 3 + lane] = vu;
    }
}

extern "C" void kernel_launch(void* const* d_in, const int* in_sizes, int n_in,
                              void* d_out, int out_size) {
    const float* h     = (const float*)d_in[0];
    const float* x     = (const float*)d_in[1];
    const float* v     = (const float*)d_in[2];
    const int*   pair  = (const int*)d_in[3];
    const float* w_in  = (const float*)d_in[4];
    const float* b_in  = (const float*)d_in[5];
    const float* w_e1  = (const float*)d_in[6];
    const float* b_e1  = (const float*)d_in[7];
    const float* w_e2  = (const float*)d_in[8];
    const float* b_e2  = (const float*)d_in[9];
    const float* w_att = (const float*)d_in[10];
    const float* b_att = (const float*)d_in[11];
    const float* w_n1  = (const float*)d_in[12];
    const float* b_n1  = (const float*)d_in[13];
    const float* w_n2  = (const float*)d_in[14];
    const float* b_n2  = (const float*)d_in[15];
    const float* w_pn1 = (const float*)d_in[16];
    const float* b_pn1 = (const float*)d_in[17];
    const float* w_pn2 = (const float*)d_in[18];
    const float* b_pn2 = (const float*)d_in[19];
    const float* w_v1  = (const float*)d_in[20];
    const float* b_v1  = (const float*)d_in[21];
    const float* w_v2  = (const float*)d_in[22];
    const float* w_xmix = (const float*)d_in[23];
    const float* w_vmix = (const float*)d_in[24];
    float* out = (float*)d_out;

    int nN = in_sizes[0] / F;
    int nE = in_sizes[3] / 2;
    if (nN > NMAX) nN = NMAX;
    if (nE > EMAX) nE = EMAX;
    const int* idx_i = pair;
    const int* idx_j = pair + nE;
    int write_xv = (out_size >= nN * (F + 6)) ? 1 : 0;

    k_init<<<128, 256>>>(nN);
    k_cvtw<<<(C * C + 255) / 256, 256>>>(w_xmix);
    k_edge<<<(nE + 31) / 32, 256>>>(h, x, idx_i, idx_j, w_in, b_in, w_e1, b_e1,
                                    w_e2, b_e2, w_att, b_att, nE, nN);
    k_scan<<<1, 1024>>>(nN);
    k_scatter<<<(nE + 255) / 256, 256>>>(idx_i, nE, nN);
    k_ssum<<<(nE * H + 255) / 256, 256>>>(idx_i, nE, nN);
    k_mix<<<(nE + 31) / 32, 256>>>(idx_i, nE, nN);
    k_node<<<(nN + 7) / 8, 256>>>(h, x, v, w_pn1, b_pn1, w_pn2, b_pn2,
                                  w_n1, b_n1, w_n2, b_n2, w_v1, b_v1, w_v2,
                                  w_vmix, out, nN, write_xv);
}